// round 14
// baseline (speedup 1.0000x reference)
#include <cuda_runtime.h>
#include <cuda_fp16.h>
#include <math.h>
#include <stdint.h>

#define N_NODES 32768
#define E_EDGES 524288
#define D_DIM   128
#define R_REL   5
#define BS_OUT  8192

// ---------------- scratch (device globals; no allocations) ----------------
__device__ __half g_xh  [(size_t)N_NODES * D_DIM];                 // fp16 layer input x
__device__ __half g_PtH [(size_t)N_NODES * R_REL * D_DIM];         // P_top fp16
__device__ __half g_PbH [(size_t)N_NODES * R_REL * D_DIM];         // P_bot fp16
__device__ __half g_wh  [(size_t)24 * 128 * 128];                  // fp16 transposed weights
__device__ __half g_xlh [(size_t)N_NODES * D_DIM];                 // fp16 xl (logits + values)
__device__ float  g_xB  [(size_t)N_NODES * D_DIM];
__device__ float  g_alpha[(size_t)E_EDGES * 4];                    // indexed by CSR pos j
__device__ int    g_cnt[N_NODES];
__device__ int    g_off[N_NODES + 1];
__device__ int    g_cur[N_NODES];
__device__ int    g_blk[32];
__device__ int    g_eid[E_EDGES];
__device__ int    g_src_r[E_EDGES];   // src in CSR order
__device__ int    g_dst_r[E_EDGES];   // dst in CSR order
__device__ int    g_et_r [E_EDGES];   // etype in CSR order

__device__ __forceinline__ float gelu_f(float x) {
    return 0.5f * x * (1.0f + erff(x * 0.7071067811865475f));
}

// ---------------- HMMA m16n8k16 (plain PTX, assembles on sm_103) ----------------
__device__ __forceinline__ void mma16816(float* c, const uint32_t* a, const uint32_t* b) {
    asm volatile("mma.sync.aligned.m16n8k16.row.col.f32.f16.f16.f32 "
        "{%0,%1,%2,%3}, {%4,%5,%6,%7}, {%8,%9}, {%0,%1,%2,%3};"
        : "+f"(c[0]), "+f"(c[1]), "+f"(c[2]), "+f"(c[3])
        : "r"(a[0]), "r"(a[1]), "r"(a[2]), "r"(a[3]), "r"(b[0]), "r"(b[1]));
}

#define PITCH 136   // halves per smem row (272 B -> conflict-free frags, 16B-aligned rows)

__device__ __forceinline__ void h8_to_f8(uint4 v, float2* o) {
    const __half2* h = (const __half2*)&v;
    o[0] = __half22float2(h[0]);
    o[1] = __half22float2(h[1]);
    o[2] = __half22float2(h[2]);
    o[3] = __half22float2(h[3]);
}

// ---------------- CSR construction (deterministic) ----------------
__global__ void k_zero_cnt() { g_cnt[blockIdx.x * 1024 + threadIdx.x] = 0; }

__global__ void k_hist(const int* __restrict__ dst) {
    int i = blockIdx.x * 256 + threadIdx.x;
    atomicAdd(&g_cnt[dst[i]], 1);
}

// parallel scan: 32 blocks x 1024 local exclusive scan + block totals
__global__ void k_scan1() {
    __shared__ int buf[1024];
    int b = blockIdx.x, t = threadIdx.x;
    int i = b * 1024 + t;
    int v = g_cnt[i];
    buf[t] = v;
    __syncthreads();
    for (int o = 1; o < 1024; o <<= 1) {
        int tv = (t >= o) ? buf[t - o] : 0;
        __syncthreads();
        buf[t] += tv;
        __syncthreads();
    }
    g_off[i] = buf[t] - v;           // local exclusive
    if (t == 1023) g_blk[b] = buf[1023];
}

__global__ void k_scan2() {
    int b = blockIdx.x, t = threadIdx.x;
    int i = b * 1024 + t;
    int base = 0;
    for (int q = 0; q < b; q++) base += g_blk[q];
    int v = g_off[i] + base;
    g_off[i] = v;
    g_cur[i] = v;
    if (b == 31 && t == 1023) g_off[N_NODES] = base + g_blk[31];
}

__global__ void k_scatter(const int* __restrict__ dst) {
    int i = blockIdx.x * 256 + threadIdx.x;
    int p = atomicAdd(&g_cur[dst[i]], 1);
    g_eid[p] = i;
}

// sort each node's segment (deterministic order) + emit reordered src/dst/et
__global__ void k_sortseg(const int* __restrict__ src, const int* __restrict__ et) {
    int n = blockIdx.x * 128 + threadIdx.x;
    int beg = g_off[n], end = g_off[n + 1];
    for (int i = beg + 1; i < end; i++) {
        int key = g_eid[i];
        int j = i - 1;
        while (j >= beg && g_eid[j] > key) { g_eid[j + 1] = g_eid[j]; j--; }
        g_eid[j + 1] = key;
    }
    for (int j = beg; j < end; j++) {
        int e = g_eid[j];
        g_src_r[j] = src[e];
        g_dst_r[j] = n;
        g_et_r[j]  = et[e];
    }
}

// ---------------- fp16 conversions ----------------
__global__ void k_x2h(const float* __restrict__ xin) {
    int i = blockIdx.x * 256 + threadIdx.x;     // over N*64 float2
    const float2* s = (const float2*)xin;
    float2 v = s[i];
    ((__half2*)g_xh)[i] = __floats2half2_rn(v.x, v.y);
}

// 24 matrices of [128][128] fp16, transposed: wt[c][k] = W[k][c]
__global__ void k_w2h(const float* __restrict__ Wl0, const float* __restrict__ We0,
                      const float* __restrict__ Wl1, const float* __restrict__ We1,
                      const float* __restrict__ rm) {
    int m = blockIdx.x;
    int layer = m / 12, j = m % 12;
    const float* sp;
    if (j == 0)       sp = layer ? We1 : We0;
    else if (j == 1)  sp = layer ? Wl1 : Wl0;
    else if (j < 7)   sp = rm + ((size_t)layer * 5 + (j - 2)) * 256 * 128;
    else              sp = rm + ((size_t)layer * 5 + (j - 7)) * 256 * 128 + 128 * 128;
    __half* dp = g_wh + (size_t)m * 16384;
    int c = threadIdx.x;
    for (int k = 0; k < 128; k++)
        dp[c * 128 + k] = __float2half_rn(sp[(size_t)k * 128 + c]);
}

// ---------------- HMMA GEMM: P sections + xl (persistent over sections) ----------------
// X tile loaded ONCE per block; loop over section list reloading only W.
// mode 0 (layer0): y=0 -> sects {0..4} (Ptop), y=1 -> {5..9 Pbot, 10 xl}
// mode 1 (layer1): y=0 -> sects {0..4} (Ptop), y=1 -> {10 xl} + {5..9 Pbot iff mt<64}
#define P_SMEM (2 * 128 * PITCH * 2)
__global__ void __launch_bounds__(256) k_gemm_P(int layer, const float* __restrict__ bl,
                                                int mode) {
    extern __shared__ __align__(16) __half smP[];
    __half* sX = smP;                 // [128][PITCH] persists
    __half* sW = smP + 128 * PITCH;   // [128][PITCH] per section
    const int tid = threadIdx.x, wid = tid >> 5, lane = tid & 31;
    const int wm = wid & 3, wn = wid >> 2;       // 4 m-warps x 2 n-warps
    const int mt = blockIdx.x, grp = blockIdx.y;

    int sects[6];
    int ns = 0;
    if (grp == 0) {
        sects[0] = 0; sects[1] = 1; sects[2] = 2; sects[3] = 3; sects[4] = 4;
        ns = 5;
    } else if (mode == 0) {
        sects[0] = 5; sects[1] = 6; sects[2] = 7; sects[3] = 8; sects[4] = 9; sects[5] = 10;
        ns = 6;
    } else {
        sects[0] = 10; ns = 1;
        if (mt < BS_OUT / 128) {
            sects[1] = 5; sects[2] = 6; sects[3] = 7; sects[4] = 8; sects[5] = 9;
            ns = 6;
        }
    }

    // load X once
    const uint4* X = (const uint4*)(g_xh + (size_t)mt * 128 * 128);
    #pragma unroll
    for (int j = 0; j < 8; j++) {
        int i = j * 256 + tid;
        int row = i >> 4, c16 = i & 15;
        *(uint4*)&sX[row * PITCH + c16 * 8] = X[i];
    }

    const int rq = lane >> 2;            // 0..7
    const int kc = (lane & 3) * 2;

    for (int si = 0; si < ns; si++) {
        const int sect = sects[si];
        const int widx = layer * 12 + (sect == 10 ? 1 : sect + 2);
        const uint4* W = (const uint4*)(g_wh + (size_t)widx * 128 * 128);
        #pragma unroll
        for (int j = 0; j < 8; j++) {
            int i = j * 256 + tid;
            int row = i >> 4, c16 = i & 15;
            *(uint4*)&sW[row * PITCH + c16 * 8] = W[i];
        }
        __syncthreads();

        float acc[2][8][4] = {};
        #pragma unroll
        for (int kch = 0; kch < 8; kch++) {
            uint32_t a[2][4];
            #pragma unroll
            for (int mi = 0; mi < 2; mi++) {
                const __half* pa = &sX[(wm * 32 + mi * 16 + rq) * PITCH + kch * 16 + kc];
                a[mi][0] = *(const uint32_t*)pa;
                a[mi][1] = *(const uint32_t*)(pa + 8 * PITCH);
                a[mi][2] = *(const uint32_t*)(pa + 8);
                a[mi][3] = *(const uint32_t*)(pa + 8 * PITCH + 8);
            }
            #pragma unroll
            for (int nt = 0; nt < 8; nt++) {
                uint32_t b[2];
                const __half* pb = &sW[(wn * 64 + nt * 8 + rq) * PITCH + kch * 16 + kc];
                b[0] = *(const uint32_t*)pb;
                b[1] = *(const uint32_t*)(pb + 8);
                mma16816(acc[0][nt], a[0], b);
                mma16816(acc[1][nt], a[1], b);
            }
        }

        if (sect == 10) {
            __half2* outh = (__half2*)g_xlh;
            #pragma unroll
            for (int mi = 0; mi < 2; mi++) {
                int row0 = mt * 128 + wm * 32 + mi * 16 + rq;
                #pragma unroll
                for (int nt = 0; nt < 8; nt++) {
                    int c = wn * 64 + nt * 8 + kc;
                    float b0 = __ldg(bl + c), b1 = __ldg(bl + c + 1);
                    int ch = c >> 1;
                    outh[(size_t)row0 * 64 + ch] =
                        __floats2half2_rn(acc[mi][nt][0] + b0, acc[mi][nt][1] + b1);
                    outh[(size_t)(row0 + 8) * 64 + ch] =
                        __floats2half2_rn(acc[mi][nt][2] + b0, acc[mi][nt][3] + b1);
                }
            }
        } else {
            int rel = (sect < 5) ? sect : sect - 5;
            __half2* out = (__half2*)(sect < 5 ? g_PtH : g_PbH);
            #pragma unroll
            for (int mi = 0; mi < 2; mi++) {
                int row0 = mt * 128 + wm * 32 + mi * 16 + rq;
                size_t o0 = ((size_t)row0 * 5 + rel) * 64;
                size_t o1 = ((size_t)(row0 + 8) * 5 + rel) * 64;
                #pragma unroll
                for (int nt = 0; nt < 8; nt++) {
                    int ch = (wn * 64 + nt * 8 + kc) >> 1;
                    out[o0 + ch] = __floats2half2_rn(acc[mi][nt][0], acc[mi][nt][1]);
                    out[o1 + ch] = __floats2half2_rn(acc[mi][nt][2], acc[mi][nt][3]);
                }
            }
        }
        __syncthreads();   // all reads of sW done before next section's fill
    }
}

// ---------------- HMMA GEMM: per-edge alpha (persistent; shfl indices, 2 syncs/tile) ----------------
#define ALPHA_SMEM (34816 * 3 + 512)
#define ALPHA_GRID 296
__global__ void __launch_bounds__(256) k_gemm_alpha(int layer, const float* __restrict__ att,
                                                    int restrict8k) {
    extern __shared__ __align__(16) char smA[];
    __half* sA  = (__half*)smA;                      // [128][PITCH]
    __half* sW  = (__half*)(smA + 34816);            // [128][PITCH] persists
    __half* sXs = (__half*)(smA + 69632);            // [128][PITCH] xsum fp16
    float* sAtt = (float*)(smA + 104448);

    const int tid = threadIdx.x, wid = tid >> 5, lane = tid & 31;

    // one-time loads: We^T tile + att
    const uint4* W = (const uint4*)(g_wh + (size_t)(layer * 12) * 128 * 128);
    #pragma unroll
    for (int j = 0; j < 8; j++) {
        int i = j * 256 + tid;
        int row = i >> 4, c16 = i & 15;
        *(uint4*)&sW[row * PITCH + c16 * 8] = W[i];
    }
    if (tid < 128) sAtt[tid] = att[tid];

    const int lim = restrict8k ? g_off[BS_OUT] : E_EDGES;
    const int rloc = wid * 16 + (lane >> 2);
    const int kc = (lane & 3) * 2;
    const int elw = wid * 16 + (lane >> 1);  // edge-in-tile this thread gathers for
    const int hf = lane & 1;

    for (int t = blockIdx.x; t < E_EDGES / 128; t += ALPHA_GRID) {
        const int ebase = t * 128;
        if (ebase >= lim) break;

        __syncthreads();   // prev tile: MMA reads of sA + epilogue reads of sXs done

        // indices: lanes 0-15 load this warp's 16 edges coalesced, then shuffle
        int srcv = 0, dstv = 0, etv = 0;
        if (lane < 16) {
            int e = ebase + wid * 16 + lane;
            srcv = g_src_r[e];
            dstv = g_dst_r[e];
            etv  = g_et_r[e];
        }
        srcv = __shfl_sync(0xffffffffu, srcv, lane >> 1);
        dstv = __shfl_sync(0xffffffffu, dstv, lane >> 1);
        etv  = __shfl_sync(0xffffffffu, etv,  lane >> 1);

        // fused gather: A = gelu(Ptop[src]+Pbot[dst]) AND xsum = xlh[src]+xlh[dst]
        {
            const uint4* PT = (const uint4*)(g_PtH + ((size_t)srcv * 5 + etv) * 128) + hf * 8;
            const uint4* PB = (const uint4*)(g_PbH + ((size_t)dstv * 5 + etv) * 128) + hf * 8;
            const uint4* xs = (const uint4*)(g_xlh + (size_t)srcv * 128) + hf * 8;
            const uint4* xd = (const uint4*)(g_xlh + (size_t)dstv * 128) + hf * 8;
            uint4* arow = (uint4*)((char*)(sA  + elw * PITCH) + hf * 128);
            uint4* orow = (uint4*)((char*)(sXs + elw * PITCH) + hf * 128);
            #pragma unroll
            for (int j = 0; j < 8; j++) {
                uint4 a4 = PT[j], b4 = PB[j];
                float2 fa[4], fb[4];
                h8_to_f8(a4, fa);
                h8_to_f8(b4, fb);
                __half2 oh[4];
                #pragma unroll
                for (int q = 0; q < 4; q++)
                    oh[q] = __floats2half2_rn(gelu_f(fa[q].x + fb[q].x),
                                              gelu_f(fa[q].y + fb[q].y));
                arow[j] = *(const uint4*)oh;
            }
            #pragma unroll
            for (int j = 0; j < 8; j++) {
                uint4 a4 = xs[j], b4 = xd[j];
                const __half2* ha = (const __half2*)&a4;
                const __half2* hb = (const __half2*)&b4;
                __half2 oh[4];
                #pragma unroll
                for (int q = 0; q < 4; q++) oh[q] = __hadd2(ha[q], hb[q]);
                orow[j] = *(const uint4*)oh;
            }
        }
        __syncthreads();

        float acc[16][4] = {};
        #pragma unroll
        for (int kch = 0; kch < 8; kch++) {
            uint32_t a[4];
            const __half* pa = &sA[rloc * PITCH + kch * 16 + kc];
            a[0] = *(const uint32_t*)pa;
            a[1] = *(const uint32_t*)(pa + 8 * PITCH);
            a[2] = *(const uint32_t*)(pa + 8);
            a[3] = *(const uint32_t*)(pa + 8 * PITCH + 8);
            #pragma unroll
            for (int nt = 0; nt < 16; nt++) {
                uint32_t b[2];
                const __half* pb = &sW[(nt * 8 + (lane >> 2)) * PITCH + kch * 16 + kc];
                b[0] = *(const uint32_t*)pb;
                b[1] = *(const uint32_t*)(pb + 8);
                mma16816(acc[nt], a, b);
            }
        }

        // epilogue: t = D + xsum; leaky; att-dot per head
        const __half2* xsumh = (const __half2*)sXs;
        const int e0 = rloc, e1 = rloc + 8;
        float hs[2][4] = {};
        #pragma unroll
        for (int nt = 0; nt < 16; nt++) {
            int c = nt * 8 + kc;
            int h = nt >> 2;
            float a0 = sAtt[c], a1 = sAtt[c + 1];
            float2 x0 = __half22float2(xsumh[(e0 * PITCH + c) >> 1]);
            float2 x1 = __half22float2(xsumh[(e1 * PITCH + c) >> 1]);
            float t0 = acc[nt][0] + x0.x;
            float t1 = acc[nt][1] + x0.y;
            float t2 = acc[nt][2] + x1.x;
            float t3 = acc[nt][3] + x1.y;
            t0 = t0 > 0.f ? t0 : 0.2f * t0;
            t1 = t1 > 0.f ? t1 : 0.2f * t1;
            t2 = t2 > 0.f ? t2 : 0.2f * t2;
            t3 = t3 > 0.f ? t3 : 0.2f * t3;
            hs[0][h] += t0 * a0 + t1 * a1;
            hs[1][h] += t2 * a0 + t3 * a1;
        }
        #pragma unroll
        for (int e = 0; e < 2; e++)
            #pragma unroll
            for (int h = 0; h < 4; h++) {
                float v = hs[e][h];
                v += __shfl_down_sync(0xffffffffu, v, 1);
                v += __shfl_down_sync(0xffffffffu, v, 2);
                hs[e][h] = v;
            }
        if ((lane & 3) == 0) {
            ((float4*)g_alpha)[ebase + e0] = make_float4(hs[0][0], hs[0][1], hs[0][2], hs[0][3]);
            ((float4*)g_alpha)[ebase + e1] = make_float4(hs[1][0], hs[1][1], hs[1][2], hs[1][3]);
        }
    }
}

// ---------------- per-node segment-softmax + aggregation ----------------
// 2 nodes/block, 64 half2-lanes per node: 4B gathers, full-sector coalescing.
__global__ void __launch_bounds__(128) k_node(const float* __restrict__ bias, int out_sel, int do_gelu) {
    const int tid = threadIdx.x;
    const int nsub = tid >> 6;              // 0/1
    const int c2 = tid & 63;                // half2 index: channels 2*c2, 2*c2+1
    const int n = blockIdx.x * 2 + nsub;
    const int h = c2 >> 4;                  // head
    const int beg = g_off[n], end = g_off[n + 1];
    const __half2* X = (const __half2*)g_xlh;
    float s = 0.f;
    float2 acc = make_float2(0.f, 0.f);
    int j = beg;
    for (; j + 3 < end; j += 4) {
        float a0 = __ldg(&g_alpha[(size_t)(j    ) * 4 + h]);
        float a1 = __ldg(&g_alpha[(size_t)(j + 1) * 4 + h]);
        float a2 = __ldg(&g_alpha[(size_t)(j + 2) * 4 + h]);
        float a3 = __ldg(&g_alpha[(size_t)(j + 3) * 4 + h]);
        int s0 = __ldg(&g_src_r[j    ]);
        int s1 = __ldg(&g_src_r[j + 1]);
        int s2 = __ldg(&g_src_r[j + 2]);
        int s3 = __ldg(&g_src_r[j + 3]);
        float2 x0 = __half22float2(__ldg(&X[(size_t)s0 * 64 + c2]));
        float2 x1 = __half22float2(__ldg(&X[(size_t)s1 * 64 + c2]));
        float2 x2 = __half22float2(__ldg(&X[(size_t)s2 * 64 + c2]));
        float2 x3 = __half22float2(__ldg(&X[(size_t)s3 * 64 + c2]));
        float w0 = __expf(a0), w1 = __expf(a1), w2 = __expf(a2), w3 = __expf(a3);
        s += (w0 + w1) + (w2 + w3);
        acc.x += (w0 * x0.x + w1 * x1.x) + (w2 * x2.x + w3 * x3.x);
        acc.y += (w0 * x0.y + w1 * x1.y) + (w2 * x2.y + w3 * x3.y);
    }
    for (; j < end; j++) {
        float a = __ldg(&g_alpha[(size_t)j * 4 + h]);
        int sp = __ldg(&g_src_r[j]);
        float2 xv = __half22float2(__ldg(&X[(size_t)sp * 64 + c2]));
        float w = __expf(a);
        s += w;
        acc.x += w * xv.x;
        acc.y += w * xv.y;
    }
    float inv = 1.f / (s + 1e-16f);
    float2 bc = ((const float2*)bias)[c2];
    float o0 = acc.x * inv + bc.x;
    float o1 = acc.y * inv + bc.y;
    if (do_gelu) { o0 = gelu_f(o0); o1 = gelu_f(o1); }
    if (out_sel) {
        ((float2*)g_xB)[(size_t)n * 64 + c2] = make_float2(o0, o1);
    } else {
        ((__half2*)g_xh)[(size_t)n * 64 + c2] = __floats2half2_rn(o0, o1);
    }
}

// ---------------- output head: 4 rows/block, 4x W register reuse ----------------
__global__ void __launch_bounds__(128) k_head(const float* __restrict__ W, const float* __restrict__ b,
                       const float* __restrict__ gam, const float* __restrict__ bet,
                       float* __restrict__ out) {
    __shared__ __align__(16) float sx[4 * 128];
    __shared__ float red[4][8];   // [row][warp] pairs packed: s1 in [0..3], s2 in [4..7]
    const int rb = blockIdx.x * 4;
    const int c = threadIdx.x;
    const int wid = c >> 5, lane = c & 31;
    #pragma unroll
    for (int r = 0; r < 4; r++)
        sx[r * 128 + c] = g_xB[(size_t)(rb + r) * 128 + c];
    __syncthreads();
    float bc = __ldg(b + c);
    float acc[4] = {bc, bc, bc, bc};
    for (int k = 0; k < 128; k += 4) {
        float w0 = __ldg(W + (k    ) * 128 + c);
        float w1 = __ldg(W + (k + 1) * 128 + c);
        float w2 = __ldg(W + (k + 2) * 128 + c);
        float w3 = __ldg(W + (k + 3) * 128 + c);
        #pragma unroll
        for (int r = 0; r < 4; r++) {
            float4 a = *(const float4*)&sx[r * 128 + k];
            acc[r] += a.x * w0 + a.y * w1 + a.z * w2 + a.w * w3;
        }
    }
    #pragma unroll
    for (int r = 0; r < 4; r++) {
        float s1 = acc[r], s2 = acc[r] * acc[r];
        #pragma unroll
        for (int o = 16; o > 0; o >>= 1) {
            s1 += __shfl_xor_sync(0xffffffffu, s1, o);
            s2 += __shfl_xor_sync(0xffffffffu, s2, o);
        }
        if (lane == 0) { red[r][wid] = s1; red[r][4 + wid] = s2; }
    }
    __syncthreads();
    #pragma unroll
    for (int r = 0; r < 4; r++) {
        float s1 = red[r][0] + red[r][1] + red[r][2] + red[r][3];
        float s2 = red[r][4] + red[r][5] + red[r][6] + red[r][7];
        float mean = s1 * (1.f / 128.f);
        float var = s2 * (1.f / 128.f) - mean * mean;
        float inv = rsqrtf(var + 1e-12f);
        out[(size_t)(rb + r) * 128 + c] =
            (acc[r] - mean) * inv * __ldg(gam + c) + __ldg(bet + c);
    }
}

// ---------------- launch ----------------
extern "C" void kernel_launch(void* const* d_in, const int* in_sizes, int n_in,
                              void* d_out, int out_size) {
    const float* embs  = (const float*)d_in[0];
    const int*   ei    = (const int*)  d_in[1];
    const int*   etyp  = (const int*)  d_in[2];
    const float* rm    = (const float*)d_in[3];
    const float* Wl0   = (const float*)d_in[4];
    const float* bl0   = (const float*)d_in[5];
    const float* We0   = (const float*)d_in[6];
    const float* att0  = (const float*)d_in[7];
    const float* bias0 = (const float*)d_in[8];
    const float* Wl1   = (const float*)d_in[9];
    const float* bl1   = (const float*)d_in[10];
    const float* We1   = (const float*)d_in[11];
    const float* att1  = (const float*)d_in[12];
    const float* bias1 = (const float*)d_in[13];
    const float* ow    = (const float*)d_in[14];
    const float* ob    = (const float*)d_in[15];
    const float* lg    = (const float*)d_in[16];
    const float* lb    = (const float*)d_in[17];
    float* out = (float*)d_out;

    const int* src = ei;
    const int* dst = ei + E_EDGES;

    cudaFuncSetAttribute(k_gemm_P, cudaFuncAttributeMaxDynamicSharedMemorySize, P_SMEM);
    cudaFuncSetAttribute(k_gemm_alpha, cudaFuncAttributeMaxDynamicSharedMemorySize, ALPHA_SMEM);

    // CSR by dst (deterministic) + reordered edge arrays
    k_zero_cnt<<<N_NODES / 1024, 1024>>>();
    k_hist<<<E_EDGES / 256, 256>>>(dst);
    k_scan1<<<32, 1024>>>();
    k_scan2<<<32, 1024>>>();
    k_scatter<<<E_EDGES / 256, 256>>>(dst);
    k_sortseg<<<N_NODES / 128, 128>>>(src, etyp);

    // weight conversion (fp16, transposed)
    k_w2h<<<24, 128>>>(Wl0, We0, Wl1, We1, rm);

    // ---- layer 0 (full graph) ----
    k_x2h<<<N_NODES * 64 / 256, 256>>>(embs);
    k_gemm_P<<<dim3(N_NODES / 128, 2), 256, P_SMEM>>>(0, bl0, /*mode=*/0);
    k_gemm_alpha<<<ALPHA_GRID, 256, ALPHA_SMEM>>>(0, att0, /*restrict8k=*/0);
    k_node<<<N_NODES / 2, 128>>>(bias0, /*out_sel=*/0, /*gelu=*/1);   // writes g_xh fp16

    // ---- layer 1 (only dst < BS_OUT contributes to the head) ----
    k_gemm_P<<<dim3(N_NODES / 128, 2), 256, P_SMEM>>>(1, bl1, /*mode=*/1);
    k_gemm_alpha<<<ALPHA_GRID, 256, ALPHA_SMEM>>>(1, att1, /*restrict8k=*/1);
    k_node<<<BS_OUT / 2, 128>>>(bias1, /*out_sel=*/1, /*gelu=*/0);    // writes g_xB fp32

    // ---- output head ----
    k_head<<<BS_OUT / 4, 128>>>(ow, ob, lg, lb, out);
}

// round 15
// speedup vs baseline: 1.0603x; 1.0603x over previous
#include <cuda_runtime.h>
#include <cuda_fp16.h>
#include <math.h>
#include <stdint.h>

#define N_NODES 32768
#define E_EDGES 524288
#define D_DIM   128
#define R_REL   5
#define BS_OUT  8192

// ---------------- scratch (device globals; no allocations) ----------------
__device__ __half g_xh  [(size_t)N_NODES * D_DIM];                 // fp16 layer input x
__device__ __half g_PtH [(size_t)N_NODES * R_REL * D_DIM];         // P_top fp16
__device__ __half g_PbH [(size_t)N_NODES * R_REL * D_DIM];         // P_bot fp16
__device__ __half g_wh  [(size_t)24 * 128 * 128];                  // fp16 transposed weights
__device__ __half g_xlh [(size_t)N_NODES * D_DIM];                 // fp16 xl (logits + values)
__device__ float  g_xB  [(size_t)N_NODES * D_DIM];
__device__ float  g_alpha[(size_t)E_EDGES * 4];                    // indexed by CSR pos j
__device__ int    g_cnt[N_NODES];
__device__ int    g_off[N_NODES + 1];
__device__ int    g_cur[N_NODES];
__device__ int    g_blk[32];
__device__ int    g_eid[E_EDGES];
__device__ int    g_src_r[E_EDGES];   // src in CSR order
__device__ int    g_dst_r[E_EDGES];   // dst in CSR order
__device__ int    g_et_r [E_EDGES];   // etype in CSR order

__device__ __forceinline__ float gelu_f(float x) {
    return 0.5f * x * (1.0f + erff(x * 0.7071067811865475f));
}

// ---------------- HMMA m16n8k16 (plain PTX, assembles on sm_103) ----------------
__device__ __forceinline__ void mma16816(float* c, const uint32_t* a, const uint32_t* b) {
    asm volatile("mma.sync.aligned.m16n8k16.row.col.f32.f16.f16.f32 "
        "{%0,%1,%2,%3}, {%4,%5,%6,%7}, {%8,%9}, {%0,%1,%2,%3};"
        : "+f"(c[0]), "+f"(c[1]), "+f"(c[2]), "+f"(c[3])
        : "r"(a[0]), "r"(a[1]), "r"(a[2]), "r"(a[3]), "r"(b[0]), "r"(b[1]));
}

#define PITCH 136   // halves per smem row (272 B -> conflict-free frags, 16B-aligned rows)

__device__ __forceinline__ void h8_to_f8(uint4 v, float2* o) {
    const __half2* h = (const __half2*)&v;
    o[0] = __half22float2(h[0]);
    o[1] = __half22float2(h[1]);
    o[2] = __half22float2(h[2]);
    o[3] = __half22float2(h[3]);
}

// ---------------- CSR construction (deterministic) ----------------
__global__ void k_zero_cnt() { g_cnt[blockIdx.x * 1024 + threadIdx.x] = 0; }

__global__ void k_hist(const int* __restrict__ dst) {
    int i = blockIdx.x * 256 + threadIdx.x;
    atomicAdd(&g_cnt[dst[i]], 1);
}

// parallel scan: 32 blocks x 1024 local exclusive scan + block totals
__global__ void k_scan1() {
    __shared__ int buf[1024];
    int b = blockIdx.x, t = threadIdx.x;
    int i = b * 1024 + t;
    int v = g_cnt[i];
    buf[t] = v;
    __syncthreads();
    for (int o = 1; o < 1024; o <<= 1) {
        int tv = (t >= o) ? buf[t - o] : 0;
        __syncthreads();
        buf[t] += tv;
        __syncthreads();
    }
    g_off[i] = buf[t] - v;           // local exclusive
    if (t == 1023) g_blk[b] = buf[1023];
}

__global__ void k_scan2() {
    int b = blockIdx.x, t = threadIdx.x;
    int i = b * 1024 + t;
    int base = 0;
    for (int q = 0; q < b; q++) base += g_blk[q];
    int v = g_off[i] + base;
    g_off[i] = v;
    g_cur[i] = v;
    if (b == 31 && t == 1023) g_off[N_NODES] = base + g_blk[31];
}

__global__ void k_scatter(const int* __restrict__ dst) {
    int i = blockIdx.x * 256 + threadIdx.x;
    int p = atomicAdd(&g_cur[dst[i]], 1);
    g_eid[p] = i;
}

// sort each node's segment (deterministic order) + emit reordered src/dst/et
__global__ void k_sortseg(const int* __restrict__ src, const int* __restrict__ et) {
    int n = blockIdx.x * 128 + threadIdx.x;
    int beg = g_off[n], end = g_off[n + 1];
    for (int i = beg + 1; i < end; i++) {
        int key = g_eid[i];
        int j = i - 1;
        while (j >= beg && g_eid[j] > key) { g_eid[j + 1] = g_eid[j]; j--; }
        g_eid[j + 1] = key;
    }
    for (int j = beg; j < end; j++) {
        int e = g_eid[j];
        g_src_r[j] = src[e];
        g_dst_r[j] = n;
        g_et_r[j]  = et[e];
    }
}

// ---------------- fp16 conversions ----------------
__global__ void k_x2h(const float* __restrict__ xin) {
    int i = blockIdx.x * 256 + threadIdx.x;     // over N*64 float2
    const float2* s = (const float2*)xin;
    float2 v = s[i];
    ((__half2*)g_xh)[i] = __floats2half2_rn(v.x, v.y);
}

// 24 matrices of [128][128] fp16, transposed: wt[c][k] = W[k][c]
__global__ void k_w2h(const float* __restrict__ Wl0, const float* __restrict__ We0,
                      const float* __restrict__ Wl1, const float* __restrict__ We1,
                      const float* __restrict__ rm) {
    int m = blockIdx.x;
    int layer = m / 12, j = m % 12;
    const float* sp;
    if (j == 0)       sp = layer ? We1 : We0;
    else if (j == 1)  sp = layer ? Wl1 : Wl0;
    else if (j < 7)   sp = rm + ((size_t)layer * 5 + (j - 2)) * 256 * 128;
    else              sp = rm + ((size_t)layer * 5 + (j - 7)) * 256 * 128 + 128 * 128;
    __half* dp = g_wh + (size_t)m * 16384;
    int c = threadIdx.x;
    for (int k = 0; k < 128; k++)
        dp[c * 128 + k] = __float2half_rn(sp[(size_t)k * 128 + c]);
}

// ---------------- HMMA GEMM: P sections + xl  (warp tile M32 x N64; R13-proven) ----------------
// sect: 0..4 Ptop rel, 5..9 Pbot rel, 10 xl(+bias)
// smode 0: s=sect (grid y=11) | smode 1: s<5 -> Ptop, s==5 -> xl (grid y=6)
// smode 2: sect = s+5 (Pbot only; grid x limited to first rows)
#define P_SMEM (2 * 128 * PITCH * 2)
__global__ void __launch_bounds__(256) k_gemm_P(int layer, const float* __restrict__ bl,
                                                int smode) {
    extern __shared__ __align__(16) __half smP[];
    __half* sX = smP;                 // [128][PITCH]
    __half* sW = smP + 128 * PITCH;
    const int tid = threadIdx.x, wid = tid >> 5, lane = tid & 31;
    const int wm = wid & 3, wn = wid >> 2;       // 4 m-warps x 2 n-warps
    const int mt = blockIdx.x, s = blockIdx.y;
    int sect;
    if (smode == 0)      sect = s;
    else if (smode == 1) sect = (s < 5) ? s : 10;
    else                 sect = s + 5;
    const int widx = layer * 12 + (sect == 10 ? 1 : sect + 2);

    const uint4* X = (const uint4*)(g_xh + (size_t)mt * 128 * 128);
    const uint4* W = (const uint4*)(g_wh + (size_t)widx * 128 * 128);
    #pragma unroll
    for (int j = 0; j < 8; j++) {
        int i = j * 256 + tid;
        int row = i >> 4, c16 = i & 15;
        *(uint4*)&sX[row * PITCH + c16 * 8] = X[i];
        *(uint4*)&sW[row * PITCH + c16 * 8] = W[i];
    }
    __syncthreads();

    float acc[2][8][4] = {};
    const int rq = lane >> 2;            // 0..7
    const int kc = (lane & 3) * 2;
    #pragma unroll
    for (int kch = 0; kch < 8; kch++) {
        uint32_t a[2][4];
        #pragma unroll
        for (int mi = 0; mi < 2; mi++) {
            const __half* pa = &sX[(wm * 32 + mi * 16 + rq) * PITCH + kch * 16 + kc];
            a[mi][0] = *(const uint32_t*)pa;
            a[mi][1] = *(const uint32_t*)(pa + 8 * PITCH);
            a[mi][2] = *(const uint32_t*)(pa + 8);
            a[mi][3] = *(const uint32_t*)(pa + 8 * PITCH + 8);
        }
        #pragma unroll
        for (int nt = 0; nt < 8; nt++) {
            uint32_t b[2];
            const __half* pb = &sW[(wn * 64 + nt * 8 + rq) * PITCH + kch * 16 + kc];
            b[0] = *(const uint32_t*)pb;
            b[1] = *(const uint32_t*)(pb + 8);
            mma16816(acc[0][nt], a[0], b);
            mma16816(acc[1][nt], a[1], b);
        }
    }

    if (sect == 10) {
        __half2* outh = (__half2*)g_xlh;
        #pragma unroll
        for (int mi = 0; mi < 2; mi++) {
            int row0 = mt * 128 + wm * 32 + mi * 16 + rq;
            #pragma unroll
            for (int nt = 0; nt < 8; nt++) {
                int c = wn * 64 + nt * 8 + kc;
                float b0 = __ldg(bl + c), b1 = __ldg(bl + c + 1);
                int ch = c >> 1;
                outh[(size_t)row0 * 64 + ch] =
                    __floats2half2_rn(acc[mi][nt][0] + b0, acc[mi][nt][1] + b1);
                outh[(size_t)(row0 + 8) * 64 + ch] =
                    __floats2half2_rn(acc[mi][nt][2] + b0, acc[mi][nt][3] + b1);
            }
        }
    } else {
        int rel = (sect < 5) ? sect : sect - 5;
        __half2* out = (__half2*)(sect < 5 ? g_PtH : g_PbH);
        #pragma unroll
        for (int mi = 0; mi < 2; mi++) {
            int row0 = mt * 128 + wm * 32 + mi * 16 + rq;
            size_t o0 = ((size_t)row0 * 5 + rel) * 64;
            size_t o1 = ((size_t)(row0 + 8) * 5 + rel) * 64;
            #pragma unroll
            for (int nt = 0; nt < 8; nt++) {
                int ch = (wn * 64 + nt * 8 + kc) >> 1;
                out[o0 + ch] = __floats2half2_rn(acc[mi][nt][0], acc[mi][nt][1]);
                out[o1 + ch] = __floats2half2_rn(acc[mi][nt][2], acc[mi][nt][3]);
            }
        }
    }
}

// ---------------- HMMA GEMM: per-edge alpha (persistent; fused gather; R13-proven) ----------------
#define ALPHA_SMEM (34816 * 3 + 512 + 1536)
#define ALPHA_GRID 296
__global__ void __launch_bounds__(256) k_gemm_alpha(int layer, const float* __restrict__ att,
                                                    int restrict8k) {
    extern __shared__ __align__(16) char smA[];
    __half* sA  = (__half*)smA;                      // [128][PITCH]
    __half* sW  = (__half*)(smA + 34816);            // [128][PITCH] persists
    __half* sXs = (__half*)(smA + 69632);            // [128][PITCH] xsum fp16
    float* sAtt = (float*)(smA + 104448);
    int* sSrc = (int*)(smA + 104960);
    int* sDst = sSrc + 128;
    int* sEt  = sDst + 128;

    const int tid = threadIdx.x, wid = tid >> 5, lane = tid & 31;

    // one-time loads: We^T tile + att
    const uint4* W = (const uint4*)(g_wh + (size_t)(layer * 12) * 128 * 128);
    #pragma unroll
    for (int j = 0; j < 8; j++) {
        int i = j * 256 + tid;
        int row = i >> 4, c16 = i & 15;
        *(uint4*)&sW[row * PITCH + c16 * 8] = W[i];
    }
    if (tid < 128) sAtt[tid] = att[tid];

    const int lim = restrict8k ? g_off[BS_OUT] : E_EDGES;
    const int rloc = wid * 16 + (lane >> 2);
    const int kc = (lane & 3) * 2;

    for (int t = blockIdx.x; t < E_EDGES / 128; t += ALPHA_GRID) {
        const int ebase = t * 128;
        if (ebase >= lim) break;

        __syncthreads();   // prev tile: MMA reads of sA + epilogue reads of sXs done
        if (tid < 128) {
            sSrc[tid] = g_src_r[ebase + tid];
            sDst[tid] = g_dst_r[ebase + tid];
            sEt[tid]  = g_et_r[ebase + tid];
        }
        __syncthreads();

        // fused gather: A = gelu(Ptop[src]+Pbot[dst]) AND xsum = xlh[src]+xlh[dst]
        {
            int el = tid >> 1, hf = tid & 1;
            const uint4* PT = (const uint4*)(g_PtH + ((size_t)sSrc[el] * 5 + sEt[el]) * 128) + hf * 8;
            const uint4* PB = (const uint4*)(g_PbH + ((size_t)sDst[el] * 5 + sEt[el]) * 128) + hf * 8;
            const uint4* xs = (const uint4*)(g_xlh + (size_t)sSrc[el] * 128) + hf * 8;
            const uint4* xd = (const uint4*)(g_xlh + (size_t)sDst[el] * 128) + hf * 8;
            uint4* arow = (uint4*)((char*)(sA  + el * PITCH) + hf * 128);
            uint4* orow = (uint4*)((char*)(sXs + el * PITCH) + hf * 128);
            #pragma unroll
            for (int j = 0; j < 8; j++) {
                uint4 a4 = PT[j], b4 = PB[j];
                float2 fa[4], fb[4];
                h8_to_f8(a4, fa);
                h8_to_f8(b4, fb);
                __half2 oh[4];
                #pragma unroll
                for (int q = 0; q < 4; q++)
                    oh[q] = __floats2half2_rn(gelu_f(fa[q].x + fb[q].x),
                                              gelu_f(fa[q].y + fb[q].y));
                arow[j] = *(const uint4*)oh;
            }
            #pragma unroll
            for (int j = 0; j < 8; j++) {
                uint4 a4 = xs[j], b4 = xd[j];
                const __half2* ha = (const __half2*)&a4;
                const __half2* hb = (const __half2*)&b4;
                __half2 oh[4];
                #pragma unroll
                for (int q = 0; q < 4; q++) oh[q] = __hadd2(ha[q], hb[q]);
                orow[j] = *(const uint4*)oh;
            }
        }
        __syncthreads();

        float acc[16][4] = {};
        #pragma unroll
        for (int kch = 0; kch < 8; kch++) {
            uint32_t a[4];
            const __half* pa = &sA[rloc * PITCH + kch * 16 + kc];
            a[0] = *(const uint32_t*)pa;
            a[1] = *(const uint32_t*)(pa + 8 * PITCH);
            a[2] = *(const uint32_t*)(pa + 8);
            a[3] = *(const uint32_t*)(pa + 8 * PITCH + 8);
            #pragma unroll
            for (int nt = 0; nt < 16; nt++) {
                uint32_t b[2];
                const __half* pb = &sW[(nt * 8 + (lane >> 2)) * PITCH + kch * 16 + kc];
                b[0] = *(const uint32_t*)pb;
                b[1] = *(const uint32_t*)(pb + 8);
                mma16816(acc[nt], a, b);
            }
        }

        // epilogue: t = D + xsum; leaky; att-dot per head
        const __half2* xsumh = (const __half2*)sXs;
        const int e0 = rloc, e1 = rloc + 8;
        float hs[2][4] = {};
        #pragma unroll
        for (int nt = 0; nt < 16; nt++) {
            int c = nt * 8 + kc;
            int h = nt >> 2;
            float a0 = sAtt[c], a1 = sAtt[c + 1];
            float2 x0 = __half22float2(xsumh[(e0 * PITCH + c) >> 1]);
            float2 x1 = __half22float2(xsumh[(e1 * PITCH + c) >> 1]);
            float t0 = acc[nt][0] + x0.x;
            float t1 = acc[nt][1] + x0.y;
            float t2 = acc[nt][2] + x1.x;
            float t3 = acc[nt][3] + x1.y;
            t0 = t0 > 0.f ? t0 : 0.2f * t0;
            t1 = t1 > 0.f ? t1 : 0.2f * t1;
            t2 = t2 > 0.f ? t2 : 0.2f * t2;
            t3 = t3 > 0.f ? t3 : 0.2f * t3;
            hs[0][h] += t0 * a0 + t1 * a1;
            hs[1][h] += t2 * a0 + t3 * a1;
        }
        #pragma unroll
        for (int e = 0; e < 2; e++)
            #pragma unroll
            for (int h = 0; h < 4; h++) {
                float v = hs[e][h];
                v += __shfl_down_sync(0xffffffffu, v, 1);
                v += __shfl_down_sync(0xffffffffu, v, 2);
                hs[e][h] = v;
            }
        if ((lane & 3) == 0) {
            ((float4*)g_alpha)[ebase + e0] = make_float4(hs[0][0], hs[0][1], hs[0][2], hs[0][3]);
            ((float4*)g_alpha)[ebase + e1] = make_float4(hs[1][0], hs[1][1], hs[1][2], hs[1][3]);
        }
    }
}

// ---------------- per-node segment-softmax + aggregation ----------------
// 2 nodes/block, 64 half2-lanes per node: 4B gathers, full-sector coalescing.
__global__ void __launch_bounds__(128) k_node(const float* __restrict__ bias, int out_sel, int do_gelu) {
    const int tid = threadIdx.x;
    const int nsub = tid >> 6;              // 0/1
    const int c2 = tid & 63;                // half2 index: channels 2*c2, 2*c2+1
    const int n = blockIdx.x * 2 + nsub;
    const int h = c2 >> 4;                  // head
    const int beg = g_off[n], end = g_off[n + 1];
    const __half2* X = (const __half2*)g_xlh;
    float s = 0.f;
    float2 acc = make_float2(0.f, 0.f);
    int j = beg;
    for (; j + 3 < end; j += 4) {
        float a0 = __ldg(&g_alpha[(size_t)(j    ) * 4 + h]);
        float a1 = __ldg(&g_alpha[(size_t)(j + 1) * 4 + h]);
        float a2 = __ldg(&g_alpha[(size_t)(j + 2) * 4 + h]);
        float a3 = __ldg(&g_alpha[(size_t)(j + 3) * 4 + h]);
        int s0 = __ldg(&g_src_r[j    ]);
        int s1 = __ldg(&g_src_r[j + 1]);
        int s2 = __ldg(&g_src_r[j + 2]);
        int s3 = __ldg(&g_src_r[j + 3]);
        float2 x0 = __half22float2(__ldg(&X[(size_t)s0 * 64 + c2]));
        float2 x1 = __half22float2(__ldg(&X[(size_t)s1 * 64 + c2]));
        float2 x2 = __half22float2(__ldg(&X[(size_t)s2 * 64 + c2]));
        float2 x3 = __half22float2(__ldg(&X[(size_t)s3 * 64 + c2]));
        float w0 = __expf(a0), w1 = __expf(a1), w2 = __expf(a2), w3 = __expf(a3);
        s += (w0 + w1) + (w2 + w3);
        acc.x += (w0 * x0.x + w1 * x1.x) + (w2 * x2.x + w3 * x3.x);
        acc.y += (w0 * x0.y + w1 * x1.y) + (w2 * x2.y + w3 * x3.y);
    }
    for (; j < end; j++) {
        float a = __ldg(&g_alpha[(size_t)j * 4 + h]);
        int sp = __ldg(&g_src_r[j]);
        float2 xv = __half22float2(__ldg(&X[(size_t)sp * 64 + c2]));
        float w = __expf(a);
        s += w;
        acc.x += w * xv.x;
        acc.y += w * xv.y;
    }
    float inv = 1.f / (s + 1e-16f);
    float2 bc = ((const float2*)bias)[c2];
    float o0 = acc.x * inv + bc.x;
    float o1 = acc.y * inv + bc.y;
    if (do_gelu) { o0 = gelu_f(o0); o1 = gelu_f(o1); }
    if (out_sel) {
        ((float2*)g_xB)[(size_t)n * 64 + c2] = make_float2(o0, o1);
    } else {
        ((__half2*)g_xh)[(size_t)n * 64 + c2] = __floats2half2_rn(o0, o1);
    }
}

// ---------------- output head: 4 rows/block, 4x W register reuse ----------------
__global__ void __launch_bounds__(128) k_head(const float* __restrict__ W, const float* __restrict__ b,
                       const float* __restrict__ gam, const float* __restrict__ bet,
                       float* __restrict__ out) {
    __shared__ __align__(16) float sx[4 * 128];
    __shared__ float red[4][8];   // [row][warp] pairs packed: s1 in [0..3], s2 in [4..7]
    const int rb = blockIdx.x * 4;
    const int c = threadIdx.x;
    const int wid = c >> 5, lane = c & 31;
    #pragma unroll
    for (int r = 0; r < 4; r++)
        sx[r * 128 + c] = g_xB[(size_t)(rb + r) * 128 + c];
    __syncthreads();
    float bc = __ldg(b + c);
    float acc[4] = {bc, bc, bc, bc};
    for (int k = 0; k < 128; k += 4) {
        float w0 = __ldg(W + (k    ) * 128 + c);
        float w1 = __ldg(W + (k + 1) * 128 + c);
        float w2 = __ldg(W + (k + 2) * 128 + c);
        float w3 = __ldg(W + (k + 3) * 128 + c);
        #pragma unroll
        for (int r = 0; r < 4; r++) {
            float4 a = *(const float4*)&sx[r * 128 + k];
            acc[r] += a.x * w0 + a.y * w1 + a.z * w2 + a.w * w3;
        }
    }
    #pragma unroll
    for (int r = 0; r < 4; r++) {
        float s1 = acc[r], s2 = acc[r] * acc[r];
        #pragma unroll
        for (int o = 16; o > 0; o >>= 1) {
            s1 += __shfl_xor_sync(0xffffffffu, s1, o);
            s2 += __shfl_xor_sync(0xffffffffu, s2, o);
        }
        if (lane == 0) { red[r][wid] = s1; red[r][4 + wid] = s2; }
    }
    __syncthreads();
    #pragma unroll
    for (int r = 0; r < 4; r++) {
        float s1 = red[r][0] + red[r][1] + red[r][2] + red[r][3];
        float s2 = red[r][4] + red[r][5] + red[r][6] + red[r][7];
        float mean = s1 * (1.f / 128.f);
        float var = s2 * (1.f / 128.f) - mean * mean;
        float inv = rsqrtf(var + 1e-12f);
        out[(size_t)(rb + r) * 128 + c] =
            (acc[r] - mean) * inv * __ldg(gam + c) + __ldg(bet + c);
    }
}

// ---------------- launch ----------------
extern "C" void kernel_launch(void* const* d_in, const int* in_sizes, int n_in,
                              void* d_out, int out_size) {
    const float* embs  = (const float*)d_in[0];
    const int*   ei    = (const int*)  d_in[1];
    const int*   etyp  = (const int*)  d_in[2];
    const float* rm    = (const float*)d_in[3];
    const float* Wl0   = (const float*)d_in[4];
    const float* bl0   = (const float*)d_in[5];
    const float* We0   = (const float*)d_in[6];
    const float* att0  = (const float*)d_in[7];
    const float* bias0 = (const float*)d_in[8];
    const float* Wl1   = (const float*)d_in[9];
    const float* bl1   = (const float*)d_in[10];
    const float* We1   = (const float*)d_in[11];
    const float* att1  = (const float*)d_in[12];
    const float* bias1 = (const float*)d_in[13];
    const float* ow    = (const float*)d_in[14];
    const float* ob    = (const float*)d_in[15];
    const float* lg    = (const float*)d_in[16];
    const float* lb    = (const float*)d_in[17];
    float* out = (float*)d_out;

    const int* src = ei;
    const int* dst = ei + E_EDGES;

    cudaFuncSetAttribute(k_gemm_P, cudaFuncAttributeMaxDynamicSharedMemorySize, P_SMEM);
    cudaFuncSetAttribute(k_gemm_alpha, cudaFuncAttributeMaxDynamicSharedMemorySize, ALPHA_SMEM);

    // fork: CSR chain on side stream, conversions + layer-0 P-GEMM on main stream
    cudaStream_t s2;
    cudaStreamCreateWithFlags(&s2, cudaStreamNonBlocking);
    cudaEvent_t eFork, eJoin;
    cudaEventCreateWithFlags(&eFork, cudaEventDisableTiming);
    cudaEventCreateWithFlags(&eJoin, cudaEventDisableTiming);

    cudaEventRecord(eFork, 0);
    cudaStreamWaitEvent(s2, eFork, 0);

    // ---- side stream: CSR by dst (deterministic) + reordered edge arrays ----
    k_zero_cnt<<<N_NODES / 1024, 1024, 0, s2>>>();
    k_hist<<<E_EDGES / 256, 256, 0, s2>>>(dst);
    k_scan1<<<32, 1024, 0, s2>>>();
    k_scan2<<<32, 1024, 0, s2>>>();
    k_scatter<<<E_EDGES / 256, 256, 0, s2>>>(dst);
    k_sortseg<<<N_NODES / 128, 128, 0, s2>>>(src, etyp);
    cudaEventRecord(eJoin, s2);

    // ---- main stream: weight conversion + layer-0 P/xl GEMM (independent of CSR) ----
    k_w2h<<<24, 128>>>(Wl0, We0, Wl1, We1, rm);
    k_x2h<<<N_NODES * 64 / 256, 256>>>(embs);
    k_gemm_P<<<dim3(N_NODES / 128, 11), 256, P_SMEM>>>(0, bl0, /*smode=*/0);

    // join: alpha needs CSR + P
    cudaStreamWaitEvent(0, eJoin, 0);

    // ---- layer 0 (full graph) ----
    k_gemm_alpha<<<ALPHA_GRID, 256, ALPHA_SMEM>>>(0, att0, /*restrict8k=*/0);
    k_node<<<N_NODES / 2, 128>>>(bias0, /*out_sel=*/0, /*gelu=*/1);   // writes g_xh fp16

    // ---- layer 1 (only dst < BS_OUT contributes to the head) ----
    k_gemm_P<<<dim3(N_NODES / 128, 6), 256, P_SMEM>>>(1, bl1, /*smode=*/1);     // Ptop + xl (all nodes)
    k_gemm_P<<<dim3(BS_OUT / 128, 5), 256, P_SMEM>>>(1, bl1, /*smode=*/2);      // Pbot (first 8192)
    k_gemm_alpha<<<ALPHA_GRID, 256, ALPHA_SMEM>>>(1, att1, /*restrict8k=*/1);
    k_node<<<BS_OUT / 2, 128>>>(bias1, /*out_sel=*/1, /*gelu=*/0);    // writes g_xB fp32

    // ---- output head ----
    k_head<<<BS_OUT / 4, 128>>>(ow, ob, lg, lb, out);

    cudaEventDestroy(eFork);
    cudaEventDestroy(eJoin);
    cudaStreamDestroy(s2);
}

// round 16
// speedup vs baseline: 1.0942x; 1.0319x over previous
#include <cuda_runtime.h>
#include <cuda_fp16.h>
#include <math.h>
#include <stdint.h>

#define N_NODES 32768
#define E_EDGES 524288
#define D_DIM   128
#define R_REL   5
#define BS_OUT  8192

// ---------------- scratch (device globals; no allocations) ----------------
__device__ __half g_xh  [(size_t)N_NODES * D_DIM];                 // fp16 layer input x
__device__ __half g_PtH [(size_t)N_NODES * R_REL * D_DIM];         // P_top fp16
__device__ __half g_PbH [(size_t)N_NODES * R_REL * D_DIM];         // P_bot fp16
__device__ __half g_wh  [(size_t)24 * 128 * 128];                  // fp16 transposed weights
__device__ __half g_xlh [(size_t)N_NODES * D_DIM];                 // fp16 xl (logits + values)
__device__ float  g_xB  [(size_t)N_NODES * D_DIM];
__device__ float  g_alpha[(size_t)E_EDGES * 4];                    // indexed by CSR pos j
__device__ int    g_cnt[N_NODES];
__device__ int    g_off[N_NODES + 1];
__device__ int    g_cur[N_NODES];
__device__ int    g_blk[32];
__device__ int    g_eid[E_EDGES];
__device__ int    g_src_r[E_EDGES];   // src in CSR order
__device__ int    g_dst_r[E_EDGES];   // dst in CSR order
__device__ int    g_et_r [E_EDGES];   // etype in CSR order

__device__ __forceinline__ float gelu_f(float x) {
    return 0.5f * x * (1.0f + erff(x * 0.7071067811865475f));
}

// ---------------- HMMA m16n8k16 (plain PTX, assembles on sm_103) ----------------
__device__ __forceinline__ void mma16816(float* c, const uint32_t* a, const uint32_t* b) {
    asm volatile("mma.sync.aligned.m16n8k16.row.col.f32.f16.f16.f32 "
        "{%0,%1,%2,%3}, {%4,%5,%6,%7}, {%8,%9}, {%0,%1,%2,%3};"
        : "+f"(c[0]), "+f"(c[1]), "+f"(c[2]), "+f"(c[3])
        : "r"(a[0]), "r"(a[1]), "r"(a[2]), "r"(a[3]), "r"(b[0]), "r"(b[1]));
}

#define PITCH 136   // halves per smem row (272 B -> conflict-free frags, 16B-aligned rows)

__device__ __forceinline__ void h8_to_f8(uint4 v, float2* o) {
    const __half2* h = (const __half2*)&v;
    o[0] = __half22float2(h[0]);
    o[1] = __half22float2(h[1]);
    o[2] = __half22float2(h[2]);
    o[3] = __half22float2(h[3]);
}

// ---------------- CSR construction (deterministic) ----------------
__global__ void k_zero_cnt() { g_cnt[blockIdx.x * 1024 + threadIdx.x] = 0; }

__global__ void k_hist(const int* __restrict__ dst) {
    int i = blockIdx.x * 256 + threadIdx.x;
    atomicAdd(&g_cnt[dst[i]], 1);
}

// parallel scan: 32 blocks x 1024 local exclusive scan + block totals
__global__ void k_scan1() {
    __shared__ int buf[1024];
    int b = blockIdx.x, t = threadIdx.x;
    int i = b * 1024 + t;
    int v = g_cnt[i];
    buf[t] = v;
    __syncthreads();
    for (int o = 1; o < 1024; o <<= 1) {
        int tv = (t >= o) ? buf[t - o] : 0;
        __syncthreads();
        buf[t] += tv;
        __syncthreads();
    }
    g_off[i] = buf[t] - v;           // local exclusive
    if (t == 1023) g_blk[b] = buf[1023];
}

__global__ void k_scan2() {
    int b = blockIdx.x, t = threadIdx.x;
    int i = b * 1024 + t;
    int base = 0;
    for (int q = 0; q < b; q++) base += g_blk[q];
    int v = g_off[i] + base;
    g_off[i] = v;
    g_cur[i] = v;
    if (b == 31 && t == 1023) g_off[N_NODES] = base + g_blk[31];
}

__global__ void k_scatter(const int* __restrict__ dst) {
    int i = blockIdx.x * 256 + threadIdx.x;
    int p = atomicAdd(&g_cur[dst[i]], 1);
    g_eid[p] = i;
}

// sort each node's segment (deterministic order) + emit reordered src/dst/et
__global__ void k_sortseg(const int* __restrict__ src, const int* __restrict__ et) {
    int n = blockIdx.x * 128 + threadIdx.x;
    int beg = g_off[n], end = g_off[n + 1];
    for (int i = beg + 1; i < end; i++) {
        int key = g_eid[i];
        int j = i - 1;
        while (j >= beg && g_eid[j] > key) { g_eid[j + 1] = g_eid[j]; j--; }
        g_eid[j + 1] = key;
    }
    for (int j = beg; j < end; j++) {
        int e = g_eid[j];
        g_src_r[j] = src[e];
        g_dst_r[j] = n;
        g_et_r[j]  = et[e];
    }
}

// ---------------- fp16 conversions ----------------
__global__ void k_x2h(const float* __restrict__ xin) {
    int i = blockIdx.x * 256 + threadIdx.x;     // over N*64 float2
    const float2* s = (const float2*)xin;
    float2 v = s[i];
    ((__half2*)g_xh)[i] = __floats2half2_rn(v.x, v.y);
}

// 24 matrices of [128][128] fp16, transposed: wt[c][k] = W[k][c]
__global__ void k_w2h(const float* __restrict__ Wl0, const float* __restrict__ We0,
                      const float* __restrict__ Wl1, const float* __restrict__ We1,
                      const float* __restrict__ rm) {
    int m = blockIdx.x;
    int layer = m / 12, j = m % 12;
    const float* sp;
    if (j == 0)       sp = layer ? We1 : We0;
    else if (j == 1)  sp = layer ? Wl1 : Wl0;
    else if (j < 7)   sp = rm + ((size_t)layer * 5 + (j - 2)) * 256 * 128;
    else              sp = rm + ((size_t)layer * 5 + (j - 7)) * 256 * 128 + 128 * 128;
    __half* dp = g_wh + (size_t)m * 16384;
    int c = threadIdx.x;
    for (int k = 0; k < 128; k++)
        dp[c * 128 + k] = __float2half_rn(sp[(size_t)k * 128 + c]);
}

// ---------------- HMMA GEMM: P sections + xl  (warp tile M32 x N64; R13-proven) ----------------
// sect: 0..4 Ptop rel, 5..9 Pbot rel, 10 xl(+bias)
// smode 0 (layer0): sect = s              (grid y=11)
// smode 3 (layer1): s<5 -> Ptop s; s==5 -> xl; s>=6 -> Pbot s-1, only mt < BS_OUT/128 (grid y=11)
#define P_SMEM (2 * 128 * PITCH * 2)
__global__ void __launch_bounds__(256) k_gemm_P(int layer, const float* __restrict__ bl,
                                                int smode) {
    const int mt = blockIdx.x, s = blockIdx.y;
    int sect;
    if (smode == 0) {
        sect = s;
    } else {
        if (s < 5)       sect = s;
        else if (s == 5) sect = 10;
        else {
            if (mt >= BS_OUT / 128) return;
            sect = s - 1;          // 6..10 -> Pbot 5..9
        }
    }
    extern __shared__ __align__(16) __half smP[];
    __half* sX = smP;                 // [128][PITCH]
    __half* sW = smP + 128 * PITCH;
    const int tid = threadIdx.x, wid = tid >> 5, lane = tid & 31;
    const int wm = wid & 3, wn = wid >> 2;       // 4 m-warps x 2 n-warps
    const int widx = layer * 12 + (sect == 10 ? 1 : sect + 2);

    const uint4* X = (const uint4*)(g_xh + (size_t)mt * 128 * 128);
    const uint4* W = (const uint4*)(g_wh + (size_t)widx * 128 * 128);
    #pragma unroll
    for (int j = 0; j < 8; j++) {
        int i = j * 256 + tid;
        int row = i >> 4, c16 = i & 15;
        *(uint4*)&sX[row * PITCH + c16 * 8] = X[i];
        *(uint4*)&sW[row * PITCH + c16 * 8] = W[i];
    }
    __syncthreads();

    float acc[2][8][4] = {};
    const int rq = lane >> 2;            // 0..7
    const int kc = (lane & 3) * 2;
    #pragma unroll
    for (int kch = 0; kch < 8; kch++) {
        uint32_t a[2][4];
        #pragma unroll
        for (int mi = 0; mi < 2; mi++) {
            const __half* pa = &sX[(wm * 32 + mi * 16 + rq) * PITCH + kch * 16 + kc];
            a[mi][0] = *(const uint32_t*)pa;
            a[mi][1] = *(const uint32_t*)(pa + 8 * PITCH);
            a[mi][2] = *(const uint32_t*)(pa + 8);
            a[mi][3] = *(const uint32_t*)(pa + 8 * PITCH + 8);
        }
        #pragma unroll
        for (int nt = 0; nt < 8; nt++) {
            uint32_t b[2];
            const __half* pb = &sW[(wn * 64 + nt * 8 + rq) * PITCH + kch * 16 + kc];
            b[0] = *(const uint32_t*)pb;
            b[1] = *(const uint32_t*)(pb + 8);
            mma16816(acc[0][nt], a[0], b);
            mma16816(acc[1][nt], a[1], b);
        }
    }

    if (sect == 10) {
        __half2* outh = (__half2*)g_xlh;
        #pragma unroll
        for (int mi = 0; mi < 2; mi++) {
            int row0 = mt * 128 + wm * 32 + mi * 16 + rq;
            #pragma unroll
            for (int nt = 0; nt < 8; nt++) {
                int c = wn * 64 + nt * 8 + kc;
                float b0 = __ldg(bl + c), b1 = __ldg(bl + c + 1);
                int ch = c >> 1;
                outh[(size_t)row0 * 64 + ch] =
                    __floats2half2_rn(acc[mi][nt][0] + b0, acc[mi][nt][1] + b1);
                outh[(size_t)(row0 + 8) * 64 + ch] =
                    __floats2half2_rn(acc[mi][nt][2] + b0, acc[mi][nt][3] + b1);
            }
        }
    } else {
        int rel = (sect < 5) ? sect : sect - 5;
        __half2* out = (__half2*)(sect < 5 ? g_PtH : g_PbH);
        #pragma unroll
        for (int mi = 0; mi < 2; mi++) {
            int row0 = mt * 128 + wm * 32 + mi * 16 + rq;
            size_t o0 = ((size_t)row0 * 5 + rel) * 64;
            size_t o1 = ((size_t)(row0 + 8) * 5 + rel) * 64;
            #pragma unroll
            for (int nt = 0; nt < 8; nt++) {
                int ch = (wn * 64 + nt * 8 + kc) >> 1;
                out[o0 + ch] = __floats2half2_rn(acc[mi][nt][0], acc[mi][nt][1]);
                out[o1 + ch] = __floats2half2_rn(acc[mi][nt][2], acc[mi][nt][3]);
            }
        }
    }
}

// ---------------- HMMA GEMM: per-edge alpha (persistent, WARP-INDEPENDENT pipeline) ----------------
// Every smem row a warp MMAs/epilogues is written by that same warp -> no block
// barriers in the tile loop; each warp runs its own gather->MMA->epilogue pipeline.
// Indices come in via lanes 0-15 coalesced loads + shfl (no smem staging).
#define ALPHA_SMEM (34816 * 3 + 512)
#define ALPHA_GRID 296
__global__ void __launch_bounds__(256) k_gemm_alpha(int layer, const float* __restrict__ att,
                                                    int restrict8k) {
    extern __shared__ __align__(16) char smA[];
    __half* sA  = (__half*)smA;                      // [128][PITCH] warp-private rows
    __half* sW  = (__half*)(smA + 34816);            // [128][PITCH] read-only after init
    __half* sXs = (__half*)(smA + 69632);            // [128][PITCH] warp-private rows
    float* sAtt = (float*)(smA + 104448);

    const int tid = threadIdx.x, wid = tid >> 5, lane = tid & 31;

    // one-time loads: We^T tile + att
    const uint4* W = (const uint4*)(g_wh + (size_t)(layer * 12) * 128 * 128);
    #pragma unroll
    for (int j = 0; j < 8; j++) {
        int i = j * 256 + tid;
        int row = i >> 4, c16 = i & 15;
        *(uint4*)&sW[row * PITCH + c16 * 8] = W[i];
    }
    if (tid < 128) sAtt[tid] = att[tid];
    __syncthreads();   // sW/sAtt visible to all warps; ONLY block barrier in kernel

    const int lim = restrict8k ? g_off[BS_OUT] : E_EDGES;
    const int rloc = wid * 16 + (lane >> 2);
    const int kc = (lane & 3) * 2;
    const int elw = wid * 16 + (lane >> 1);  // edge-in-tile this thread gathers for
    const int hf = lane & 1;

    for (int t = blockIdx.x; t < E_EDGES / 128; t += ALPHA_GRID) {
        const int ebase = t * 128;
        if (ebase >= lim) break;

        __syncwarp();   // WAR: prev tile's reads of this warp's sA/sXs rows done

        // indices: lanes 0-15 load this warp's 16 edges coalesced, then shuffle
        int srcv = 0, dstv = 0, etv = 0;
        if (lane < 16) {
            int e = ebase + wid * 16 + lane;
            srcv = g_src_r[e];
            dstv = g_dst_r[e];
            etv  = g_et_r[e];
        }
        srcv = __shfl_sync(0xffffffffu, srcv, lane >> 1);
        dstv = __shfl_sync(0xffffffffu, dstv, lane >> 1);
        etv  = __shfl_sync(0xffffffffu, etv,  lane >> 1);

        // fused gather: A = gelu(Ptop[src]+Pbot[dst]) AND xsum = xlh[src]+xlh[dst]
        {
            const uint4* PT = (const uint4*)(g_PtH + ((size_t)srcv * 5 + etv) * 128) + hf * 8;
            const uint4* PB = (const uint4*)(g_PbH + ((size_t)dstv * 5 + etv) * 128) + hf * 8;
            const uint4* xs = (const uint4*)(g_xlh + (size_t)srcv * 128) + hf * 8;
            const uint4* xd = (const uint4*)(g_xlh + (size_t)dstv * 128) + hf * 8;
            uint4* arow = (uint4*)((char*)(sA  + elw * PITCH) + hf * 128);
            uint4* orow = (uint4*)((char*)(sXs + elw * PITCH) + hf * 128);
            #pragma unroll
            for (int j = 0; j < 8; j++) {
                uint4 a4 = PT[j], b4 = PB[j];
                float2 fa[4], fb[4];
                h8_to_f8(a4, fa);
                h8_to_f8(b4, fb);
                __half2 oh[4];
                #pragma unroll
                for (int q = 0; q < 4; q++)
                    oh[q] = __floats2half2_rn(gelu_f(fa[q].x + fb[q].x),
                                              gelu_f(fa[q].y + fb[q].y));
                arow[j] = *(const uint4*)oh;
            }
            #pragma unroll
            for (int j = 0; j < 8; j++) {
                uint4 a4 = xs[j], b4 = xd[j];
                const __half2* ha = (const __half2*)&a4;
                const __half2* hb = (const __half2*)&b4;
                __half2 oh[4];
                #pragma unroll
                for (int q = 0; q < 4; q++) oh[q] = __hadd2(ha[q], hb[q]);
                orow[j] = *(const uint4*)oh;
            }
        }
        __syncwarp();   // RAW: this warp's sA/sXs rows visible to its own lanes

        float acc[16][4] = {};
        #pragma unroll
        for (int kch = 0; kch < 8; kch++) {
            uint32_t a[4];
            const __half* pa = &sA[rloc * PITCH + kch * 16 + kc];
            a[0] = *(const uint32_t*)pa;
            a[1] = *(const uint32_t*)(pa + 8 * PITCH);
            a[2] = *(const uint32_t*)(pa + 8);
            a[3] = *(const uint32_t*)(pa + 8 * PITCH + 8);
            #pragma unroll
            for (int nt = 0; nt < 16; nt++) {
                uint32_t b[2];
                const __half* pb = &sW[(nt * 8 + (lane >> 2)) * PITCH + kch * 16 + kc];
                b[0] = *(const uint32_t*)pb;
                b[1] = *(const uint32_t*)(pb + 8);
                mma16816(acc[nt], a, b);
            }
        }

        // epilogue: t = D + xsum; leaky; att-dot per head (reads own warp's sXs rows)
        const __half2* xsumh = (const __half2*)sXs;
        const int e0 = rloc, e1 = rloc + 8;
        float hs[2][4] = {};
        #pragma unroll
        for (int nt = 0; nt < 16; nt++) {
            int c = nt * 8 + kc;
            int h = nt >> 2;
            float a0 = sAtt[c], a1 = sAtt[c + 1];
            float2 x0 = __half22float2(xsumh[(e0 * PITCH + c) >> 1]);
            float2 x1 = __half22float2(xsumh[(e1 * PITCH + c) >> 1]);
            float t0 = acc[nt][0] + x0.x;
            float t1 = acc[nt][1] + x0.y;
            float t2 = acc[nt][2] + x1.x;
            float t3 = acc[nt][3] + x1.y;
            t0 = t0 > 0.f ? t0 : 0.2f * t0;
            t1 = t1 > 0.f ? t1 : 0.2f * t1;
            t2 = t2 > 0.f ? t2 : 0.2f * t2;
            t3 = t3 > 0.f ? t3 : 0.2f * t3;
            hs[0][h] += t0 * a0 + t1 * a1;
            hs[1][h] += t2 * a0 + t3 * a1;
        }
        #pragma unroll
        for (int e = 0; e < 2; e++)
            #pragma unroll
            for (int h = 0; h < 4; h++) {
                float v = hs[e][h];
                v += __shfl_down_sync(0xffffffffu, v, 1);
                v += __shfl_down_sync(0xffffffffu, v, 2);
                hs[e][h] = v;
            }
        if ((lane & 3) == 0) {
            ((float4*)g_alpha)[ebase + e0] = make_float4(hs[0][0], hs[0][1], hs[0][2], hs[0][3]);
            ((float4*)g_alpha)[ebase + e1] = make_float4(hs[1][0], hs[1][1], hs[1][2], hs[1][3]);
        }
    }
}

// ---------------- per-node segment-softmax + aggregation ----------------
// 2 nodes/block, 64 half2-lanes per node: 4B gathers, full-sector coalescing.
__global__ void __launch_bounds__(128) k_node(const float* __restrict__ bias, int out_sel, int do_gelu) {
    const int tid = threadIdx.x;
    const int nsub = tid >> 6;              // 0/1
    const int c2 = tid & 63;                // half2 index: channels 2*c2, 2*c2+1
    const int n = blockIdx.x * 2 + nsub;
    const int h = c2 >> 4;                  // head
    const int beg = g_off[n], end = g_off[n + 1];
    const __half2* X = (const __half2*)g_xlh;
    float s = 0.f;
    float2 acc = make_float2(0.f, 0.f);
    int j = beg;
    for (; j + 3 < end; j += 4) {
        float a0 = __ldg(&g_alpha[(size_t)(j    ) * 4 + h]);
        float a1 = __ldg(&g_alpha[(size_t)(j + 1) * 4 + h]);
        float a2 = __ldg(&g_alpha[(size_t)(j + 2) * 4 + h]);
        float a3 = __ldg(&g_alpha[(size_t)(j + 3) * 4 + h]);
        int s0 = __ldg(&g_src_r[j    ]);
        int s1 = __ldg(&g_src_r[j + 1]);
        int s2 = __ldg(&g_src_r[j + 2]);
        int s3 = __ldg(&g_src_r[j + 3]);
        float2 x0 = __half22float2(__ldg(&X[(size_t)s0 * 64 + c2]));
        float2 x1 = __half22float2(__ldg(&X[(size_t)s1 * 64 + c2]));
        float2 x2 = __half22float2(__ldg(&X[(size_t)s2 * 64 + c2]));
        float2 x3 = __half22float2(__ldg(&X[(size_t)s3 * 64 + c2]));
        float w0 = __expf(a0), w1 = __expf(a1), w2 = __expf(a2), w3 = __expf(a3);
        s += (w0 + w1) + (w2 + w3);
        acc.x += (w0 * x0.x + w1 * x1.x) + (w2 * x2.x + w3 * x3.x);
        acc.y += (w0 * x0.y + w1 * x1.y) + (w2 * x2.y + w3 * x3.y);
    }
    for (; j < end; j++) {
        float a = __ldg(&g_alpha[(size_t)j * 4 + h]);
        int sp = __ldg(&g_src_r[j]);
        float2 xv = __half22float2(__ldg(&X[(size_t)sp * 64 + c2]));
        float w = __expf(a);
        s += w;
        acc.x += w * xv.x;
        acc.y += w * xv.y;
    }
    float inv = 1.f / (s + 1e-16f);
    float2 bc = ((const float2*)bias)[c2];
    float o0 = acc.x * inv + bc.x;
    float o1 = acc.y * inv + bc.y;
    if (do_gelu) { o0 = gelu_f(o0); o1 = gelu_f(o1); }
    if (out_sel) {
        ((float2*)g_xB)[(size_t)n * 64 + c2] = make_float2(o0, o1);
    } else {
        ((__half2*)g_xh)[(size_t)n * 64 + c2] = __floats2half2_rn(o0, o1);
    }
}

// ---------------- output head: 4 rows/block, 4x W register reuse ----------------
__global__ void __launch_bounds__(128) k_head(const float* __restrict__ W, const float* __restrict__ b,
                       const float* __restrict__ gam, const float* __restrict__ bet,
                       float* __restrict__ out) {
    __shared__ __align__(16) float sx[4 * 128];
    __shared__ float red[4][8];   // [row][warp] pairs packed: s1 in [0..3], s2 in [4..7]
    const int rb = blockIdx.x * 4;
    const int c = threadIdx.x;
    const int wid = c >> 5, lane = c & 31;
    #pragma unroll
    for (int r = 0; r < 4; r++)
        sx[r * 128 + c] = g_xB[(size_t)(rb + r) * 128 + c];
    __syncthreads();
    float bc = __ldg(b + c);
    float acc[4] = {bc, bc, bc, bc};
    for (int k = 0; k < 128; k += 4) {
        float w0 = __ldg(W + (k    ) * 128 + c);
        float w1 = __ldg(W + (k + 1) * 128 + c);
        float w2 = __ldg(W + (k + 2) * 128 + c);
        float w3 = __ldg(W + (k + 3) * 128 + c);
        #pragma unroll
        for (int r = 0; r < 4; r++) {
            float4 a = *(const float4*)&sx[r * 128 + k];
            acc[r] += a.x * w0 + a.y * w1 + a.z * w2 + a.w * w3;
        }
    }
    #pragma unroll
    for (int r = 0; r < 4; r++) {
        float s1 = acc[r], s2 = acc[r] * acc[r];
        #pragma unroll
        for (int o = 16; o > 0; o >>= 1) {
            s1 += __shfl_xor_sync(0xffffffffu, s1, o);
            s2 += __shfl_xor_sync(0xffffffffu, s2, o);
        }
        if (lane == 0) { red[r][wid] = s1; red[r][4 + wid] = s2; }
    }
    __syncthreads();
    #pragma unroll
    for (int r = 0; r < 4; r++) {
        float s1 = red[r][0] + red[r][1] + red[r][2] + red[r][3];
        float s2 = red[r][4] + red[r][5] + red[r][6] + red[r][7];
        float mean = s1 * (1.f / 128.f);
        float var = s2 * (1.f / 128.f) - mean * mean;
        float inv = rsqrtf(var + 1e-12f);
        out[(size_t)(rb + r) * 128 + c] =
            (acc[r] - mean) * inv * __ldg(gam + c) + __ldg(bet + c);
    }
}

// ---------------- launch ----------------
extern "C" void kernel_launch(void* const* d_in, const int* in_sizes, int n_in,
                              void* d_out, int out_size) {
    const float* embs  = (const float*)d_in[0];
    const int*   ei    = (const int*)  d_in[1];
    const int*   etyp  = (const int*)  d_in[2];
    const float* rm    = (const float*)d_in[3];
    const float* Wl0   = (const float*)d_in[4];
    const float* bl0   = (const float*)d_in[5];
    const float* We0   = (const float*)d_in[6];
    const float* att0  = (const float*)d_in[7];
    const float* bias0 = (const float*)d_in[8];
    const float* Wl1   = (const float*)d_in[9];
    const float* bl1   = (const float*)d_in[10];
    const float* We1   = (const float*)d_in[11];
    const float* att1  = (const float*)d_in[12];
    const float* bias1 = (const float*)d_in[13];
    const float* ow    = (const float*)d_in[14];
    const float* ob    = (const float*)d_in[15];
    const float* lg    = (const float*)d_in[16];
    const float* lb    = (const float*)d_in[17];
    float* out = (float*)d_out;

    const int* src = ei;
    const int* dst = ei + E_EDGES;

    cudaFuncSetAttribute(k_gemm_P, cudaFuncAttributeMaxDynamicSharedMemorySize, P_SMEM);
    cudaFuncSetAttribute(k_gemm_alpha, cudaFuncAttributeMaxDynamicSharedMemorySize, ALPHA_SMEM);

    // fork: CSR chain on side stream, conversions + layer-0 P-GEMM on main stream
    cudaStream_t s2;
    cudaStreamCreateWithFlags(&s2, cudaStreamNonBlocking);
    cudaEvent_t eFork, eJoin;
    cudaEventCreateWithFlags(&eFork, cudaEventDisableTiming);
    cudaEventCreateWithFlags(&eJoin, cudaEventDisableTiming);

    cudaEventRecord(eFork, 0);
    cudaStreamWaitEvent(s2, eFork, 0);

    // ---- side stream: CSR by dst (deterministic) + reordered edge arrays ----
    k_zero_cnt<<<N_NODES / 1024, 1024, 0, s2>>>();
    k_hist<<<E_EDGES / 256, 256, 0, s2>>>(dst);
    k_scan1<<<32, 1024, 0, s2>>>();
    k_scan2<<<32, 1024, 0, s2>>>();
    k_scatter<<<E_EDGES / 256, 256, 0, s2>>>(dst);
    k_sortseg<<<N_NODES / 128, 128, 0, s2>>>(src, etyp);
    cudaEventRecord(eJoin, s2);

    // ---- main stream: weight conversion + layer-0 P/xl GEMM (independent of CSR) ----
    k_x2h<<<N_NODES * 64 / 256, 256>>>(embs);
    k_w2h<<<24, 128>>>(Wl0, We0, Wl1, We1, rm);
    k_gemm_P<<<dim3(N_NODES / 128, 11), 256, P_SMEM>>>(0, bl0, /*smode=*/0);

    // join: alpha needs CSR + P
    cudaStreamWaitEvent(0, eJoin, 0);

    // ---- layer 0 (full graph) ----
    k_gemm_alpha<<<ALPHA_GRID, 256, ALPHA_SMEM>>>(0, att0, /*restrict8k=*/0);
    k_node<<<N_NODES / 2, 128>>>(bias0, /*out_sel=*/0, /*gelu=*/1);   // writes g_xh fp16

    // ---- layer 1 (only dst < BS_OUT contributes to the head; single merged launch) ----
    k_gemm_P<<<dim3(N_NODES / 128, 11), 256, P_SMEM>>>(1, bl1, /*smode=*/3);
    k_gemm_alpha<<<ALPHA_GRID, 256, ALPHA_SMEM>>>(1, att1, /*restrict8k=*/1);
    k_node<<<BS_OUT / 2, 128>>>(bias1, /*out_sel=*/1, /*gelu=*/0);    // writes g_xB fp32

    // ---- output head ----
    k_head<<<BS_OUT / 4, 128>>>(ow, ob, lg, lb, out);

    cudaEventDestroy(eFork);
    cudaEventDestroy(eJoin);
    cudaStreamDestroy(s2);
}